// round 16
// baseline (speedup 1.0000x reference)
#include <cuda_runtime.h>
#include <cuda_fp16.h>
#include <cstdint>

#define NN   4096
#define INF  256
#define HD   256   // H*D
#define H    4
#define D    64

// ---------------- device scratch (no cudaMalloc allowed) ----------------
__device__ float4   g_fi [H * NN];                   // (si, e^si, e^.2si, 0) fp32
__device__ __align__(16) uint4  g_fjp[H * NN / 2];   // per (h, j-pair): {sj2, e^sj2, e^.2sj2, 0}
__device__ __align__(16) __half g_ht [H * D * NN];   // h transposed per head: [h][f][j]
__device__ __align__(16) uint32_t g_adjb[NN * NN / 32];  // packed adjacency bits
__device__ __align__(16) __half g_xh [NN * INF];     // x in fp16
__device__ __align__(16) __half g_wh [HD * INF];     // W^T in fp16: [n][k]

// ---------------- smem layouts ----------------
#define PSB    272                    // aggregate B row stride (136 halfs)
#define BBUF   17408                  // one B buffer: 64 rows x 272
#define SM_FJP 0                      // 4 x uint4[64] = 4096
#define SM_BS  4096                   // 4 x 17408 = 69632
#define SM_TOT 73728
#define RED_OFF 4096                  // combine scratch aliases B buffers post-loop

#define PSG    144                    // gemm tile row stride (72 halfs)
#define GA0    0
#define GA1    18432
#define GB0    36864
#define GB1    46080
#define GSB    55296
#define GTOT   56320

#define GEMM_BLKS ((NN / 128) * H)    // 128
#define PACK_BLKS (NN * NN / 512 / 8) // 4096 (each warp packs 512 ints)

__device__ __forceinline__ uint32_t smem_u32(const void* p) {
    uint32_t a;
    asm("{ .reg .u64 t; cvta.to.shared.u64 t, %1; cvt.u32.u64 %0, t; }"
        : "=r"(a) : "l"(p));
    return a;
}

__device__ __forceinline__ void cpa16(uint32_t dst, const void* src) {
    asm volatile("cp.async.cg.shared.global [%0], [%1], 16;" :: "r"(dst), "l"(src));
}

// NOTE: non-volatile — pure register computation, lets ptxas pipeline across k-steps
__device__ __forceinline__ void mma16816(float* c,
                                         uint32_t a0, uint32_t a1, uint32_t a2, uint32_t a3,
                                         uint32_t b0, uint32_t b1) {
    asm("mma.sync.aligned.m16n8k16.row.col.f32.f16.f16.f32 "
        "{%0,%1,%2,%3}, {%4,%5,%6,%7}, {%8,%9}, {%0,%1,%2,%3};"
        : "+f"(c[0]), "+f"(c[1]), "+f"(c[2]), "+f"(c[3])
        : "r"(a0), "r"(a1), "r"(a2), "r"(a3), "r"(b0), "r"(b1));
}

__device__ __forceinline__ void ldsm4(uint32_t& r0, uint32_t& r1, uint32_t& r2, uint32_t& r3,
                                      uint32_t addr) {
    asm volatile("ldmatrix.sync.aligned.m8n8.x4.shared.b16 {%0,%1,%2,%3}, [%4];"
                 : "=r"(r0), "=r"(r1), "=r"(r2), "=r"(r3) : "r"(addr));
}

__device__ __forceinline__ __half2 h2bits(uint32_t v) { return *(__half2*)&v; }
__device__ __forceinline__ uint32_t bitsh2(__half2 v) { return *(uint32_t*)&v; }

__device__ __forceinline__ uint32_t wcalc(uint4 q, uint32_t bb,
                                          __half2 negsi2, __half2 epi2, __half2 eni2) {
    __half2 cond = __hgt2(h2bits(q.x), negsi2);
    __half2 ph   = __hmul2(epi2, h2bits(q.y));
    __half2 pl   = __hmul2(eni2, h2bits(q.z));
    __half2 w    = __hfma2(cond, __hsub2(ph, pl), pl);
    uint32_t mb  = (bb & 1u) * 0x3C00u + (bb & 2u) * 0x1E000000u;
    return bitsh2(__hmul2(w, h2bits(mb)));
}

// ---------------- K_cvt: fp16 copies of x and W^T (coalesced both ways) ----------------
__global__ __launch_bounds__(256) void cvt_inputs(const float* __restrict__ x,
                                                  const float* __restrict__ W) {
    const int b = blockIdx.x, t = threadIdx.x;
    if (b < 512) {                     // x: 1M elems; thread converts 8 floats
        const size_t id = ((size_t)(b << 8) + t) * 8;
        float4 v0 = *(const float4*)(x + id);
        float4 v1 = *(const float4*)(x + id + 4);
        uint4 o;
        o.x = bitsh2(__floats2half2_rn(v0.x, v0.y));
        o.y = bitsh2(__floats2half2_rn(v0.z, v0.w));
        o.z = bitsh2(__floats2half2_rn(v1.x, v1.y));
        o.w = bitsh2(__floats2half2_rn(v1.z, v1.w));
        *(uint4*)(g_xh + id) = o;
    } else {                           // W^T: 64x64 tile transpose via smem
        __shared__ __half sbuf[64][68];
        const int tile = b - 512;
        const int tk = (tile >> 2) << 6, tn = (tile & 3) << 6;
#pragma unroll
        for (int i = 0; i < 4; ++i) {
            int q = t + (i << 8);          // 0..1023 float4s
            int k = q >> 4, n4 = q & 15;
            float4 v = __ldg((const float4*)&W[(size_t)(tk + k) * HD + tn + (n4 << 2)]);
            sbuf[k][(n4 << 2) + 0] = __float2half(v.x);
            sbuf[k][(n4 << 2) + 1] = __float2half(v.y);
            sbuf[k][(n4 << 2) + 2] = __float2half(v.z);
            sbuf[k][(n4 << 2) + 3] = __float2half(v.w);
        }
        __syncthreads();
#pragma unroll
        for (int i = 0; i < 2; ++i) {
            int idx = t + (i << 8);        // 0..511 uint4s (8 halfs each)
            int n = idx >> 3, k8 = (idx & 7) << 3;
            uint32_t pk[4];
#pragma unroll
            for (int p = 0; p < 4; ++p) {
                __half2 h;
                h.x = sbuf[k8 + 2 * p][n];
                h.y = sbuf[k8 + 2 * p + 1][n];
                pk[p] = bitsh2(h);
            }
            *(uint4*)&g_wh[(size_t)(tn + n) * INF + tk + k8] =
                make_uint4(pk[0], pk[1], pk[2], pk[3]);
        }
    }
}

// ---------------- K1: merged HMMA gemm (+scores, +fp16 transpose) AND adj pack ----------------
__global__ __launch_bounds__(256, 1) void gemm_pack(const float* __restrict__ a1,
                                                    const float* __restrict__ a2,
                                                    const int* __restrict__ adj) {
    const int t = threadIdx.x;
    if (blockIdx.x >= GEMM_BLKS) {
        const int wg   = (blockIdx.x - GEMM_BLKS) * 8 + (t >> 5);
        const int lane = t & 31;
        const size_t base = (size_t)wg << 9;
        uint32_t bits[16];
#pragma unroll
        for (int r = 0; r < 16; ++r) {
            int v = __ldg(adj + base + (r << 5) + lane);
            bits[r] = __ballot_sync(0xffffffffu, v > 0);
        }
        if (lane == 0) {
#pragma unroll
            for (int r = 0; r < 4; ++r)
                *(uint4*)&g_adjb[(base >> 5) + (r << 2)] =
                    make_uint4(bits[4 * r], bits[4 * r + 1],
                               bits[4 * r + 2], bits[4 * r + 3]);
        }
        return;
    }

    extern __shared__ char sm[];
    const uint32_t sm_u = smem_u32(sm);
    const int lane = t & 31, wid = t >> 5;
    const int head = blockIdx.x & 3;
    const int m0   = (blockIdx.x >> 2) << 7;

    auto stageA = [&](int kc) {
        const uint32_t Au = sm_u + ((kc & 1) ? GA1 : GA0);
#pragma unroll
        for (int r = 0; r < 4; ++r) {
            int id  = t + (r << 8);
            int row = id >> 3, u = id & 7;
            cpa16(Au + row * PSG + (u << 4),
                  g_xh + (size_t)(m0 + row) * INF + (kc << 6) + (u << 3));
        }
    };
    auto stageB = [&](int kc) {
        const uint32_t Bu = sm_u + ((kc & 1) ? GB1 : GB0);
#pragma unroll
        for (int r = 0; r < 2; ++r) {
            int id  = t + (r << 8);
            int row = id >> 3, u = id & 7;
            cpa16(Bu + row * PSG + (u << 4),
                  g_wh + (size_t)((head << 6) + row) * INF + (kc << 6) + (u << 3));
        }
    };

    stageA(0); stageB(0);
    asm volatile("cp.async.commit_group;");

    const int g  = lane >> 2;
    const int t2 = (lane & 3) << 1;
    const uint32_t lrow = ((lane >> 3) & 1) * 8 + (lane & 7);
    const uint32_t lcol = (lane >> 4) * 16;

    float acc[8][4];
#pragma unroll
    for (int nb = 0; nb < 8; nb++)
#pragma unroll
        for (int q = 0; q < 4; q++) acc[nb][q] = 0.f;

    for (int kc = 0; kc < 4; ++kc) {
        asm volatile("cp.async.wait_group 0;" ::: "memory");
        __syncthreads();
        if (kc < 3) {
            stageA(kc + 1); stageB(kc + 1);
            asm volatile("cp.async.commit_group;");
        }
        const uint32_t Au = sm_u + ((kc & 1) ? GA1 : GA0);
        const uint32_t Bu = sm_u + ((kc & 1) ? GB1 : GB0);
        const uint32_t a_base  = Au + (wid * 16 + lrow) * PSG + lcol;
        const uint32_t b_base0 = Bu + (lrow +  0) * PSG + lcol;
        const uint32_t b_base1 = Bu + (lrow + 16) * PSG + lcol;
        const uint32_t b_base2 = Bu + (lrow + 32) * PSG + lcol;
        const uint32_t b_base3 = Bu + (lrow + 48) * PSG + lcol;
#pragma unroll
        for (int ks = 0; ks < 4; ++ks) {
            const uint32_t ko = ks * 32;
            uint32_t a0, a1r, a2r, a3;
            uint32_t p0[4], p1[4];
            ldsm4(a0, a1r, a2r, a3, a_base + ko);
            ldsm4(p0[0], p0[1], p0[2], p0[3], b_base0 + ko);
            ldsm4(p1[0], p1[1], p1[2], p1[3], b_base1 + ko);
            mma16816(acc[0], a0, a1r, a2r, a3, p0[0], p0[2]);
            mma16816(acc[1], a0, a1r, a2r, a3, p0[1], p0[3]);
            ldsm4(p0[0], p0[1], p0[2], p0[3], b_base2 + ko);
            mma16816(acc[2], a0, a1r, a2r, a3, p1[0], p1[2]);
            mma16816(acc[3], a0, a1r, a2r, a3, p1[1], p1[3]);
            ldsm4(p1[0], p1[1], p1[2], p1[3], b_base3 + ko);
            mma16816(acc[4], a0, a1r, a2r, a3, p0[0], p0[2]);
            mma16816(acc[5], a0, a1r, a2r, a3, p0[1], p0[3]);
            mma16816(acc[6], a0, a1r, a2r, a3, p1[0], p1[2]);
            mma16816(acc[7], a0, a1r, a2r, a3, p1[1], p1[3]);
        }
    }

    float s1r0 = 0.f, s1r1 = 0.f, s2r0 = 0.f, s2r1 = 0.f;
#pragma unroll
    for (int nb = 0; nb < 8; ++nb) {
        const int c0 = (nb << 3) + t2;
        float a1a = __ldg(a1 + c0), a1b = __ldg(a1 + c0 + 1);
        float a2a = __ldg(a2 + c0), a2b = __ldg(a2 + c0 + 1);
        s1r0 += acc[nb][0] * a1a + acc[nb][1] * a1b;
        s2r0 += acc[nb][0] * a2a + acc[nb][1] * a2b;
        s1r1 += acc[nb][2] * a1a + acc[nb][3] * a1b;
        s2r1 += acc[nb][2] * a2a + acc[nb][3] * a2b;
    }
#pragma unroll
    for (int m = 1; m < 4; m <<= 1) {
        s1r0 += __shfl_xor_sync(0xffffffffu, s1r0, m);
        s2r0 += __shfl_xor_sync(0xffffffffu, s2r0, m);
        s1r1 += __shfl_xor_sync(0xffffffffu, s1r1, m);
        s2r1 += __shfl_xor_sync(0xffffffffu, s2r1, m);
    }

    __syncthreads();
    __half* Ts = (__half*)(sm);
    float2* sb = (float2*)(sm + GSB);
    if ((lane & 3) == 0) {
        const int r = wid * 16 + g;
        sb[r]     = make_float2(s1r0, s2r0);
        sb[r + 8] = make_float2(s1r1, s2r1);
    }
    {
        const int r = wid * 16 + g;
#pragma unroll
        for (int nb = 0; nb < 8; ++nb) {
            const int c0 = (nb << 3) + t2;
            Ts[c0 * 136 + r]           = __float2half(acc[nb][0]);
            Ts[(c0 + 1) * 136 + r]     = __float2half(acc[nb][1]);
            Ts[c0 * 136 + r + 8]       = __float2half(acc[nb][2]);
            Ts[(c0 + 1) * 136 + r + 8] = __float2half(acc[nb][3]);
        }
    }
    __syncthreads();

    if (t < 128) {
        float2 s = sb[t];
        g_fi[head * NN + m0 + t] =
            make_float4(s.x, __expf(s.x), __expf(0.2f * s.x), 0.f);
    } else if (t < 192) {
        const int p = t - 128;
        float2 sa = sb[2 * p], sbv = sb[2 * p + 1];
        uint4 o;
        o.x = bitsh2(__floats2half2_rn(sa.y, sbv.y));
        o.y = bitsh2(__floats2half2_rn(__expf(sa.y), __expf(sbv.y)));
        o.z = bitsh2(__floats2half2_rn(__expf(0.2f * sa.y), __expf(0.2f * sbv.y)));
        o.w = 0;
        g_fjp[head * (NN / 2) + (m0 >> 1) + p] = o;
    }
#pragma unroll
    for (int r = 0; r < 4; ++r) {
        int id = t + (r << 8);
        int f  = id >> 4, u = id & 15;
        uint4 v = *(const uint4*)(sm + f * PSB + (u << 4));
        *(uint4*)(g_ht + (((size_t)((head << 6) + f)) << 12) + m0 + (u << 3)) = v;
    }
}

// ---------------- K3: dual-warpgroup pipelined HMMA aggregation ----------------
__global__ __launch_bounds__(256, 2) void aggregate_mma(float* __restrict__ out) {
    extern __shared__ char sm[];
    const int t    = threadIdx.x;
    const int lane = t & 31, wid = t >> 5;
    const int grp  = wid >> 2;
    const int wl   = wid & 3;
    const int head = blockIdx.x & 3;
    const int i0   = (blockIdx.x >> 2) << 6;

    const uint32_t sm_u  = smem_u32(sm);
    const uint32_t fjp_u = sm_u + SM_FJP;
    const uint32_t Bb_u  = sm_u + SM_BS;
    const uint4* __restrict__ fjs = (const uint4*)sm;   // [4 bufs][64]

    const int g   = lane >> 2;
    const int c2q = lane & 3;
    const int t2  = c2q << 1;

    const int rA = i0 + wl * 16 + g;
    const float4 fiA = __ldg(&g_fi[head * NN + rA]);
    const float4 fiB = __ldg(&g_fi[head * NN + rA + 8]);
    const __half2 negA = __float2half2_rn(-fiA.x), epA = __float2half2_rn(fiA.y),
                  enA  = __float2half2_rn(fiA.z);
    const __half2 negB = __float2half2_rn(-fiB.x), epB = __float2half2_rn(fiB.y),
                  enB  = __float2half2_rn(fiB.z);
    const uint32_t* __restrict__ adjA = g_adjb + ((size_t)rA << 7);
    const uint32_t* __restrict__ adjB = g_adjb + ((size_t)(rA + 8) << 7);

    auto stage = [&](int cc) {
        const int j0  = cc << 7;
        const int buf = cc & 3;
        if (t < 64)
            cpa16(fjp_u + buf * 1024 + t * 16,
                  (const char*)(g_fjp + head * (NN / 2) + (j0 >> 1) + t));
#pragma unroll
        for (int r = 0; r < 4; ++r) {
            int id = t + (r << 8);
            int f  = id >> 4, u = id & 15;
            cpa16(Bb_u + buf * BBUF + f * PSB + (u << 4),
                  g_ht + (((size_t)((head << 6) + f)) << 12) + j0 + (u << 3));
        }
    };

    stage(0); stage(1);
    asm volatile("cp.async.commit_group;");

    uint32_t awA[4], awB[4];
    {
        const int o0 = grp << 2;
#pragma unroll
        for (int q = 0; q < 4; ++q) { awA[q] = __ldg(adjA + o0 + q); awB[q] = __ldg(adjB + o0 + q); }
    }

    const uint32_t lrow = ((lane >> 3) & 1) * 8 + (lane & 7);
    const uint32_t lcol = (lane >> 4) * 16;
    const uint32_t zfrag = (lane < 4) ? 0x3C003C00u : 0u;

    float acc[8][4];
    float accz[4];
#pragma unroll
    for (int nb = 0; nb < 8; nb++)
#pragma unroll
        for (int q = 0; q < 4; q++) acc[nb][q] = 0.f;
#pragma unroll
    for (int q = 0; q < 4; q++) accz[q] = 0.f;

    for (int s = 0; s < 16; ++s) {
        asm volatile("cp.async.wait_group 0;" ::: "memory");
        __syncthreads();
        if (s < 15) {
            stage(2 * s + 2); stage(2 * s + 3);
            asm volatile("cp.async.commit_group;");
        }
        uint32_t nxA[4], nxB[4];
        if (s < 15) {
            const int o = ((s + 1) << 3) + (grp << 2);
#pragma unroll
            for (int q = 0; q < 4; ++q) { nxA[q] = __ldg(adjA + o + q); nxB[q] = __ldg(adjB + o + q); }
        }

        const int buf = (2 * s + grp) & 3;
        const uint32_t Bu = Bb_u + buf * BBUF;
        const uint32_t b_base0 = Bu + (lrow +  0) * PSB + lcol;
        const uint32_t b_base1 = Bu + (lrow + 16) * PSB + lcol;
        const uint32_t b_base2 = Bu + (lrow + 32) * PSB + lcol;
        const uint32_t b_base3 = Bu + (lrow + 48) * PSB + lcol;
        const uint4* fq = fjs + buf * 64 + c2q;

#pragma unroll
        for (int ks = 0; ks < 8; ++ks) {
            const uint32_t ko = ks * 32;
            uint32_t p0[4], p1[4];
            ldsm4(p0[0], p0[1], p0[2], p0[3], b_base0 + ko);
            ldsm4(p1[0], p1[1], p1[2], p1[3], b_base1 + ko);

            const uint4 qav = fq[ks * 8];        // compiler-scheduled LDS
            const uint4 qbv = fq[ks * 8 + 4];
            const int pos = ((ks & 1) << 4) + t2;
            const uint32_t wA = awA[ks >> 1], wB = awB[ks >> 1];
            uint32_t a0 = wcalc(qav, (wA >> pos) & 3u,       negA, epA, enA);
            uint32_t a1 = wcalc(qav, (wB >> pos) & 3u,       negB, epB, enB);
            uint32_t a2 = wcalc(qbv, (wA >> (pos + 8)) & 3u, negA, epA, enA);
            uint32_t a3 = wcalc(qbv, (wB >> (pos + 8)) & 3u, negB, epB, enB);

            mma16816(acc[0], a0, a1, a2, a3, p0[0], p0[2]);
            mma16816(acc[1], a0, a1, a2, a3, p0[1], p0[3]);
            ldsm4(p0[0], p0[1], p0[2], p0[3], b_base2 + ko);
            mma16816(acc[2], a0, a1, a2, a3, p1[0], p1[2]);
            mma16816(acc[3], a0, a1, a2, a3, p1[1], p1[3]);
            ldsm4(p1[0], p1[1], p1[2], p1[3], b_base3 + ko);
            mma16816(accz, a0, a1, a2, a3, zfrag, zfrag);
            mma16816(acc[4], a0, a1, a2, a3, p0[0], p0[2]);
            mma16816(acc[5], a0, a1, a2, a3, p0[1], p0[3]);
            mma16816(acc[6], a0, a1, a2, a3, p1[0], p1[2]);
            mma16816(acc[7], a0, a1, a2, a3, p1[1], p1[3]);
        }
#pragma unroll
        for (int q = 0; q < 4; ++q) { awA[q] = nxA[q]; awB[q] = nxB[q]; }
    }

    // ---- combine the two warp-groups ----
    __syncthreads();
    float* red = (float*)(sm + RED_OFF);
    if (grp == 1) {
        const int base = (t & 127) * 37;
#pragma unroll
        for (int nb = 0; nb < 8; ++nb)
#pragma unroll
            for (int q = 0; q < 4; ++q) red[base + nb * 4 + q] = acc[nb][q];
#pragma unroll
        for (int q = 0; q < 4; ++q) red[base + 32 + q] = accz[q];
    }
    __syncthreads();
    if (grp == 0) {
        const int base = t * 37;
#pragma unroll
        for (int nb = 0; nb < 8; ++nb)
#pragma unroll
            for (int q = 0; q < 4; ++q) acc[nb][q] += red[base + nb * 4 + q];
#pragma unroll
        for (int q = 0; q < 4; ++q) accz[q] += red[base + 32 + q];

        const float z0 = __shfl_sync(0xffffffffu, accz[0], lane & ~3);
        const float z1 = __shfl_sync(0xffffffffu, accz[2], lane & ~3);
        const float rz0 = 1.0f / z0;
        const float rz1 = 1.0f / z1;

        const int r0 = wl * 16 + g;
        float* const ob = out + (size_t)(i0 + r0) * HD + (head << 6) + t2;
#pragma unroll
        for (int nb = 0; nb < 8; ++nb) {
            *(float2*)(ob + nb * 8)          = make_float2(acc[nb][0] * rz0, acc[nb][1] * rz0);
            *(float2*)(ob + nb * 8 + 8 * HD) = make_float2(acc[nb][2] * rz1, acc[nb][3] * rz1);
        }
    }
}

extern "C" void kernel_launch(void* const* d_in, const int* in_sizes, int n_in,
                              void* d_out, int out_size) {
    const float* x   = (const float*)d_in[0];
    const int*   adj = (const int*)  d_in[1];
    const float* W   = (const float*)d_in[2];
    const float* a1  = (const float*)d_in[3];
    const float* a2  = (const float*)d_in[4];
    float* out = (float*)d_out;

    cudaFuncSetAttribute(gemm_pack,     cudaFuncAttributeMaxDynamicSharedMemorySize, GTOT);
    cudaFuncSetAttribute(aggregate_mma, cudaFuncAttributeMaxDynamicSharedMemorySize, SM_TOT);

    cvt_inputs   <<<512 + 16, 256>>>(x, W);
    gemm_pack    <<<GEMM_BLKS + PACK_BLKS, 256, GTOT>>>(a1, a2, adj);
    aggregate_mma<<<(NN / 64) * H, 256, SM_TOT>>>(out);
}

// round 17
// speedup vs baseline: 1.0195x; 1.0195x over previous
#include <cuda_runtime.h>
#include <cuda_fp16.h>
#include <cstdint>

#define NN   4096
#define INF  256
#define HD   256   // H*D
#define H    4
#define D    64
#define LOG2E 1.4426950408889634f

// ---------------- device scratch (no cudaMalloc allowed) ----------------
__device__ __half    g_sil[H * NN];                  // si * log2e, fp16
__device__ __align__(16) uint32_t g_sjl[H * NN / 2]; // per (h, j-pair): half2(sj*log2e)
__device__ __align__(16) __half g_ht [H * D * NN];   // h transposed per head: [h][f][j]
__device__ __align__(16) uint32_t g_adjb[NN * NN / 32];  // packed adjacency bits
__device__ __align__(16) __half g_xh [NN * INF];     // x in fp16
__device__ __align__(16) __half g_wh [HD * INF];     // W^T in fp16: [n][k]

// ---------------- smem layouts ----------------
#define PSB    272                    // aggregate B row stride (136 halfs)
#define BBUF   17408                  // one B buffer: 64 rows x 272
#define SM_FJL 0                      // 4 x 256B = 1024
#define SM_BS  1024                   // 4 x 17408 = 69632
#define SM_TOT 70656
#define RED_OFF 1024                  // combine scratch aliases B buffers post-loop

#define PSG    144                    // gemm tile row stride (72 halfs)
#define GA0    0
#define GA1    18432
#define GB0    36864
#define GB1    46080
#define GSB    55296
#define GTOT   56320

#define GEMM_BLKS ((NN / 128) * H)    // 128
#define PACK_BLKS (NN * NN / 512 / 8) // 4096 (each warp packs 512 ints)

__device__ __forceinline__ uint32_t smem_u32(const void* p) {
    uint32_t a;
    asm("{ .reg .u64 t; cvta.to.shared.u64 t, %1; cvt.u32.u64 %0, t; }"
        : "=r"(a) : "l"(p));
    return a;
}

__device__ __forceinline__ void cpa16(uint32_t dst, const void* src) {
    asm volatile("cp.async.cg.shared.global [%0], [%1], 16;" :: "r"(dst), "l"(src));
}

__device__ __forceinline__ void mma16816(float* c,
                                         uint32_t a0, uint32_t a1, uint32_t a2, uint32_t a3,
                                         uint32_t b0, uint32_t b1) {
    asm("mma.sync.aligned.m16n8k16.row.col.f32.f16.f16.f32 "
        "{%0,%1,%2,%3}, {%4,%5,%6,%7}, {%8,%9}, {%0,%1,%2,%3};"
        : "+f"(c[0]), "+f"(c[1]), "+f"(c[2]), "+f"(c[3])
        : "r"(a0), "r"(a1), "r"(a2), "r"(a3), "r"(b0), "r"(b1));
}

__device__ __forceinline__ void ldsm4(uint32_t& r0, uint32_t& r1, uint32_t& r2, uint32_t& r3,
                                      uint32_t addr) {
    asm volatile("ldmatrix.sync.aligned.m8n8.x4.shared.b16 {%0,%1,%2,%3}, [%4];"
                 : "=r"(r0), "=r"(r1), "=r"(r2), "=r"(r3) : "r"(addr));
}

__device__ __forceinline__ __half2 h2bits(uint32_t v) { return *(__half2*)&v; }
__device__ __forceinline__ uint32_t bitsh2(__half2 v) { return *(uint32_t*)&v; }

// exp2 on packed fp16x2 (MUFU pipe)
__device__ __forceinline__ uint32_t h2exp2(uint32_t x) {
    uint32_t r;
    asm("ex2.approx.f16x2 %0, %1;" : "=r"(r) : "r"(x));
    return r;
}

// half2 mask from 2 adjacency bits: bit0 -> low half 0xFFFF, bit1 -> high half
__device__ __forceinline__ uint32_t amask(uint32_t bb) {
    return (bb & 1u) * 0xFFFFu + (bb & 2u) * 0x7FFF8000u;
}

// ---------------- K_cvt: fp16 copies of x and W^T (coalesced both ways) ----------------
__global__ __launch_bounds__(256) void cvt_inputs(const float* __restrict__ x,
                                                  const float* __restrict__ W) {
    const int b = blockIdx.x, t = threadIdx.x;
    if (b < 512) {                     // x: 1M elems; thread converts 8 floats
        const size_t id = ((size_t)(b << 8) + t) * 8;
        float4 v0 = *(const float4*)(x + id);
        float4 v1 = *(const float4*)(x + id + 4);
        uint4 o;
        o.x = bitsh2(__floats2half2_rn(v0.x, v0.y));
        o.y = bitsh2(__floats2half2_rn(v0.z, v0.w));
        o.z = bitsh2(__floats2half2_rn(v1.x, v1.y));
        o.w = bitsh2(__floats2half2_rn(v1.z, v1.w));
        *(uint4*)(g_xh + id) = o;
    } else {                           // W^T: 64x64 tile transpose via smem
        __shared__ __half sbuf[64][68];
        const int tile = b - 512;
        const int tk = (tile >> 2) << 6, tn = (tile & 3) << 6;
#pragma unroll
        for (int i = 0; i < 4; ++i) {
            int q = t + (i << 8);
            int k = q >> 4, n4 = q & 15;
            float4 v = __ldg((const float4*)&W[(size_t)(tk + k) * HD + tn + (n4 << 2)]);
            sbuf[k][(n4 << 2) + 0] = __float2half(v.x);
            sbuf[k][(n4 << 2) + 1] = __float2half(v.y);
            sbuf[k][(n4 << 2) + 2] = __float2half(v.z);
            sbuf[k][(n4 << 2) + 3] = __float2half(v.w);
        }
        __syncthreads();
#pragma unroll
        for (int i = 0; i < 2; ++i) {
            int idx = t + (i << 8);
            int n = idx >> 3, k8 = (idx & 7) << 3;
            uint32_t pk[4];
#pragma unroll
            for (int p = 0; p < 4; ++p) {
                __half2 h;
                h.x = sbuf[k8 + 2 * p][n];
                h.y = sbuf[k8 + 2 * p + 1][n];
                pk[p] = bitsh2(h);
            }
            *(uint4*)&g_wh[(size_t)(tn + n) * INF + tk + k8] =
                make_uint4(pk[0], pk[1], pk[2], pk[3]);
        }
    }
}

// ---------------- K1: merged HMMA gemm (+scores, +fp16 transpose) AND adj pack ----------------
__global__ __launch_bounds__(256, 1) void gemm_pack(const float* __restrict__ a1,
                                                    const float* __restrict__ a2,
                                                    const int* __restrict__ adj) {
    const int t = threadIdx.x;
    if (blockIdx.x >= GEMM_BLKS) {
        const int wg   = (blockIdx.x - GEMM_BLKS) * 8 + (t >> 5);
        const int lane = t & 31;
        const size_t base = (size_t)wg << 9;
        uint32_t bits[16];
#pragma unroll
        for (int r = 0; r < 16; ++r) {
            int v = __ldg(adj + base + (r << 5) + lane);
            bits[r] = __ballot_sync(0xffffffffu, v > 0);
        }
        if (lane == 0) {
#pragma unroll
            for (int r = 0; r < 4; ++r)
                *(uint4*)&g_adjb[(base >> 5) + (r << 2)] =
                    make_uint4(bits[4 * r], bits[4 * r + 1],
                               bits[4 * r + 2], bits[4 * r + 3]);
        }
        return;
    }

    extern __shared__ char sm[];
    const uint32_t sm_u = smem_u32(sm);
    const int lane = t & 31, wid = t >> 5;
    const int head = blockIdx.x & 3;
    const int m0   = (blockIdx.x >> 2) << 7;

    auto stageA = [&](int kc) {
        const uint32_t Au = sm_u + ((kc & 1) ? GA1 : GA0);
#pragma unroll
        for (int r = 0; r < 4; ++r) {
            int id  = t + (r << 8);
            int row = id >> 3, u = id & 7;
            cpa16(Au + row * PSG + (u << 4),
                  g_xh + (size_t)(m0 + row) * INF + (kc << 6) + (u << 3));
        }
    };
    auto stageB = [&](int kc) {
        const uint32_t Bu = sm_u + ((kc & 1) ? GB1 : GB0);
#pragma unroll
        for (int r = 0; r < 2; ++r) {
            int id  = t + (r << 8);
            int row = id >> 3, u = id & 7;
            cpa16(Bu + row * PSG + (u << 4),
                  g_wh + (size_t)((head << 6) + row) * INF + (kc << 6) + (u << 3));
        }
    };

    stageA(0); stageB(0);
    asm volatile("cp.async.commit_group;");

    const int g  = lane >> 2;
    const int t2 = (lane & 3) << 1;
    const uint32_t lrow = ((lane >> 3) & 1) * 8 + (lane & 7);
    const uint32_t lcol = (lane >> 4) * 16;

    float acc[8][4];
#pragma unroll
    for (int nb = 0; nb < 8; nb++)
#pragma unroll
        for (int q = 0; q < 4; q++) acc[nb][q] = 0.f;

    for (int kc = 0; kc < 4; ++kc) {
        asm volatile("cp.async.wait_group 0;" ::: "memory");
        __syncthreads();
        if (kc < 3) {
            stageA(kc + 1); stageB(kc + 1);
            asm volatile("cp.async.commit_group;");
        }
        const uint32_t Au = sm_u + ((kc & 1) ? GA1 : GA0);
        const uint32_t Bu = sm_u + ((kc & 1) ? GB1 : GB0);
        const uint32_t a_base  = Au + (wid * 16 + lrow) * PSG + lcol;
        const uint32_t b_base0 = Bu + (lrow +  0) * PSG + lcol;
        const uint32_t b_base1 = Bu + (lrow + 16) * PSG + lcol;
        const uint32_t b_base2 = Bu + (lrow + 32) * PSG + lcol;
        const uint32_t b_base3 = Bu + (lrow + 48) * PSG + lcol;
#pragma unroll
        for (int ks = 0; ks < 4; ++ks) {
            const uint32_t ko = ks * 32;
            uint32_t a0, a1r, a2r, a3;
            uint32_t p0[4], p1[4];
            ldsm4(a0, a1r, a2r, a3, a_base + ko);
            ldsm4(p0[0], p0[1], p0[2], p0[3], b_base0 + ko);
            ldsm4(p1[0], p1[1], p1[2], p1[3], b_base1 + ko);
            mma16816(acc[0], a0, a1r, a2r, a3, p0[0], p0[2]);
            mma16816(acc[1], a0, a1r, a2r, a3, p0[1], p0[3]);
            ldsm4(p0[0], p0[1], p0[2], p0[3], b_base2 + ko);
            mma16816(acc[2], a0, a1r, a2r, a3, p1[0], p1[2]);
            mma16816(acc[3], a0, a1r, a2r, a3, p1[1], p1[3]);
            ldsm4(p1[0], p1[1], p1[2], p1[3], b_base3 + ko);
            mma16816(acc[4], a0, a1r, a2r, a3, p0[0], p0[2]);
            mma16816(acc[5], a0, a1r, a2r, a3, p0[1], p0[3]);
            mma16816(acc[6], a0, a1r, a2r, a3, p1[0], p1[2]);
            mma16816(acc[7], a0, a1r, a2r, a3, p1[1], p1[3]);
        }
    }

    float s1r0 = 0.f, s1r1 = 0.f, s2r0 = 0.f, s2r1 = 0.f;
#pragma unroll
    for (int nb = 0; nb < 8; ++nb) {
        const int c0 = (nb << 3) + t2;
        float a1a = __ldg(a1 + c0), a1b = __ldg(a1 + c0 + 1);
        float a2a = __ldg(a2 + c0), a2b = __ldg(a2 + c0 + 1);
        s1r0 += acc[nb][0] * a1a + acc[nb][1] * a1b;
        s2r0 += acc[nb][0] * a2a + acc[nb][1] * a2b;
        s1r1 += acc[nb][2] * a1a + acc[nb][3] * a1b;
        s2r1 += acc[nb][2] * a2a + acc[nb][3] * a2b;
    }
#pragma unroll
    for (int m = 1; m < 4; m <<= 1) {
        s1r0 += __shfl_xor_sync(0xffffffffu, s1r0, m);
        s2r0 += __shfl_xor_sync(0xffffffffu, s2r0, m);
        s1r1 += __shfl_xor_sync(0xffffffffu, s1r1, m);
        s2r1 += __shfl_xor_sync(0xffffffffu, s2r1, m);
    }

    __syncthreads();
    __half* Ts = (__half*)(sm);
    float2* sb = (float2*)(sm + GSB);
    if ((lane & 3) == 0) {
        const int r = wid * 16 + g;
        sb[r]     = make_float2(s1r0, s2r0);
        sb[r + 8] = make_float2(s1r1, s2r1);
    }
    {
        const int r = wid * 16 + g;
#pragma unroll
        for (int nb = 0; nb < 8; ++nb) {
            const int c0 = (nb << 3) + t2;
            Ts[c0 * 136 + r]           = __float2half(acc[nb][0]);
            Ts[(c0 + 1) * 136 + r]     = __float2half(acc[nb][1]);
            Ts[c0 * 136 + r + 8]       = __float2half(acc[nb][2]);
            Ts[(c0 + 1) * 136 + r + 8] = __float2half(acc[nb][3]);
        }
    }
    __syncthreads();

    if (t < 128) {                     // si * log2e, fp16
        g_sil[head * NN + m0 + t] = __float2half(sb[t].x * LOG2E);
    } else if (t < 192) {              // sj pair * log2e, half2
        const int p = t - 128;
        g_sjl[head * (NN / 2) + (m0 >> 1) + p] =
            bitsh2(__floats2half2_rn(sb[2 * p].y * LOG2E, sb[2 * p + 1].y * LOG2E));
    }
#pragma unroll
    for (int r = 0; r < 4; ++r) {
        int id = t + (r << 8);
        int f  = id >> 4, u = id & 15;
        uint4 v = *(const uint4*)(sm + f * PSB + (u << 4));
        *(uint4*)(g_ht + (((size_t)((head << 6) + f)) << 12) + m0 + (u << 3)) = v;
    }
}

// ---------------- K3: dual-warpgroup pipelined HMMA aggregation ----------------
// Weight = exp2(max(t, 0.2t)), t = (si+sj)*log2e, via ex2.approx.f16x2 (MUFU).
__global__ __launch_bounds__(256, 2) void aggregate_mma(float* __restrict__ out) {
    extern __shared__ char sm[];
    const int t    = threadIdx.x;
    const int lane = t & 31, wid = t >> 5;
    const int grp  = wid >> 2;
    const int wl   = wid & 3;
    const int head = blockIdx.x & 3;
    const int i0   = (blockIdx.x >> 2) << 6;

    const uint32_t sm_u  = smem_u32(sm);
    const uint32_t fjl_u = sm_u + SM_FJL;
    const uint32_t Bb_u  = sm_u + SM_BS;
    const uint32_t* __restrict__ fjl = (const uint32_t*)sm;   // [4 bufs][64]

    const int g   = lane >> 2;
    const int c2q = lane & 3;
    const int t2  = c2q << 1;

    const int rA = i0 + wl * 16 + g;
    const __half2 silA2 = __half2half2(g_sil[head * NN + rA]);
    const __half2 silB2 = __half2half2(g_sil[head * NN + rA + 8]);
    const __half2 c02   = __float2half2_rn(0.2f);
    const uint32_t* __restrict__ adjA = g_adjb + ((size_t)rA << 7);
    const uint32_t* __restrict__ adjB = g_adjb + ((size_t)(rA + 8) << 7);

    auto stage = [&](int cc) {
        const int j0  = cc << 7;
        const int buf = cc & 3;
        if (t < 16)
            cpa16(fjl_u + buf * 256 + t * 16,
                  (const char*)(g_sjl + head * (NN / 2) + (j0 >> 1) + t * 4));
#pragma unroll
        for (int r = 0; r < 4; ++r) {
            int id = t + (r << 8);
            int f  = id >> 4, u = id & 15;
            cpa16(Bb_u + buf * BBUF + f * PSB + (u << 4),
                  g_ht + (((size_t)((head << 6) + f)) << 12) + j0 + (u << 3));
        }
    };

    stage(0); stage(1);
    asm volatile("cp.async.commit_group;");

    uint32_t awA[4], awB[4];
    {
        const int o0 = grp << 2;
#pragma unroll
        for (int q = 0; q < 4; ++q) { awA[q] = __ldg(adjA + o0 + q); awB[q] = __ldg(adjB + o0 + q); }
    }

    const uint32_t lrow = ((lane >> 3) & 1) * 8 + (lane & 7);
    const uint32_t lcol = (lane >> 4) * 16;
    const uint32_t zfrag = (lane < 4) ? 0x3C003C00u : 0u;

    float acc[8][4];
    float accz[4];
#pragma unroll
    for (int nb = 0; nb < 8; nb++)
#pragma unroll
        for (int q = 0; q < 4; q++) acc[nb][q] = 0.f;
#pragma unroll
    for (int q = 0; q < 4; q++) accz[q] = 0.f;

    for (int s = 0; s < 16; ++s) {
        asm volatile("cp.async.wait_group 0;" ::: "memory");
        __syncthreads();
        if (s < 15) {
            stage(2 * s + 2); stage(2 * s + 3);
            asm volatile("cp.async.commit_group;");
        }
        uint32_t nxA[4], nxB[4];
        if (s < 15) {
            const int o = ((s + 1) << 3) + (grp << 2);
#pragma unroll
            for (int q = 0; q < 4; ++q) { nxA[q] = __ldg(adjA + o + q); nxB[q] = __ldg(adjB + o + q); }
        }

        const int buf = (2 * s + grp) & 3;
        const uint32_t Bu = Bb_u + buf * BBUF;
        const uint32_t b_base0 = Bu + (lrow +  0) * PSB + lcol;
        const uint32_t b_base1 = Bu + (lrow + 16) * PSB + lcol;
        const uint32_t b_base2 = Bu + (lrow + 32) * PSB + lcol;
        const uint32_t b_base3 = Bu + (lrow + 48) * PSB + lcol;
        const uint32_t* fq = fjl + buf * 64 + c2q;

#pragma unroll
        for (int ks = 0; ks < 8; ++ks) {
            const uint32_t ko = ks * 32;
            uint32_t p0[4], p1[4];
            ldsm4(p0[0], p0[1], p0[2], p0[3], b_base0 + ko);
            ldsm4(p1[0], p1[1], p1[2], p1[3], b_base1 + ko);

            // weight gen: t = si'+sj'; w = exp2(max(t, 0.2t)) & adjmask
            const uint32_t u0 = fq[ks * 8];
            const uint32_t u1 = fq[ks * 8 + 4];
            __half2 tA0 = __hadd2(silA2, h2bits(u0));
            __half2 tB0 = __hadd2(silB2, h2bits(u0));
            __half2 tA1 = __hadd2(silA2, h2bits(u1));
            __half2 tB1 = __hadd2(silB2, h2bits(u1));
            tA0 = __hmax2(tA0, __hmul2(tA0, c02));
            tB0 = __hmax2(tB0, __hmul2(tB0, c02));
            tA1 = __hmax2(tA1, __hmul2(tA1, c02));
            tB1 = __hmax2(tB1, __hmul2(tB1, c02));
            const int pos = ((ks & 1) << 4) + t2;
            const uint32_t wA = awA[ks >> 1], wB = awB[ks >> 1];
            uint32_t a0 = h2exp2(bitsh2(tA0)) & amask((wA >> pos) & 3u);
            uint32_t a1 = h2exp2(bitsh2(tB0)) & amask((wB >> pos) & 3u);
            uint32_t a2 = h2exp2(bitsh2(tA1)) & amask((wA >> (pos + 8)) & 3u);
            uint32_t a3 = h2exp2(bitsh2(tB1)) & amask((wB >> (pos + 8)) & 3u);

            mma16816(acc[0], a0, a1, a2, a3, p0[0], p0[2]);
            mma16816(acc[1], a0, a1, a2, a3, p0[1], p0[3]);
            ldsm4(p0[0], p0[1], p0[2], p0[3], b_base2 + ko);
            mma16816(acc[2], a0, a1, a2, a3, p1[0], p1[2]);
            mma16816(acc[3], a0, a1, a2, a3, p1[1], p1[3]);
            ldsm4(p1[0], p1[1], p1[2], p1[3], b_base3 + ko);
            mma16816(accz, a0, a1, a2, a3, zfrag, zfrag);
            mma16816(acc[4], a0, a1, a2, a3, p0[0], p0[2]);
            mma16816(acc[5], a0, a1, a2, a3, p0[1], p0[3]);
            mma16816(acc[6], a0, a1, a2, a3, p1[0], p1[2]);
            mma16816(acc[7], a0, a1, a2, a3, p1[1], p1[3]);
        }
#pragma unroll
        for (int q = 0; q < 4; ++q) { awA[q] = nxA[q]; awB[q] = nxB[q]; }
    }

    // ---- combine the two warp-groups ----
    __syncthreads();
    float* red = (float*)(sm + RED_OFF);
    if (grp == 1) {
        const int base = (t & 127) * 37;
#pragma unroll
        for (int nb = 0; nb < 8; ++nb)
#pragma unroll
            for (int q = 0; q < 4; ++q) red[base + nb * 4 + q] = acc[nb][q];
#pragma unroll
        for (int q = 0; q < 4; ++q) red[base + 32 + q] = accz[q];
    }
    __syncthreads();
    if (grp == 0) {
        const int base = t * 37;
#pragma unroll
        for (int nb = 0; nb < 8; ++nb)
#pragma unroll
            for (int q = 0; q < 4; ++q) acc[nb][q] += red[base + nb * 4 + q];
#pragma unroll
        for (int q = 0; q < 4; ++q) accz[q] += red[base + 32 + q];

        const float z0 = __shfl_sync(0xffffffffu, accz[0], lane & ~3);
        const float z1 = __shfl_sync(0xffffffffu, accz[2], lane & ~3);
        const float rz0 = 1.0f / z0;
        const float rz1 = 1.0f / z1;

        const int r0 = wl * 16 + g;
        float* const ob = out + (size_t)(i0 + r0) * HD + (head << 6) + t2;
#pragma unroll
        for (int nb = 0; nb < 8; ++nb) {
            *(float2*)(ob + nb * 8)          = make_float2(acc[nb][0] * rz0, acc[nb][1] * rz0);
            *(float2*)(ob + nb * 8 + 8 * HD) = make_float2(acc[nb][2] * rz1, acc[nb][3] * rz1);
        }
    }
}

extern "C" void kernel_launch(void* const* d_in, const int* in_sizes, int n_in,
                              void* d_out, int out_size) {
    const float* x   = (const float*)d_in[0];
    const int*   adj = (const int*)  d_in[1];
    const float* W   = (const float*)d_in[2];
    const float* a1  = (const float*)d_in[3];
    const float* a2  = (const float*)d_in[4];
    float* out = (float*)d_out;

    cudaFuncSetAttribute(gemm_pack,     cudaFuncAttributeMaxDynamicSharedMemorySize, GTOT);
    cudaFuncSetAttribute(aggregate_mma, cudaFuncAttributeMaxDynamicSharedMemorySize, SM_TOT);

    cvt_inputs   <<<512 + 16, 256>>>(x, W);
    gemm_pack    <<<GEMM_BLKS + PACK_BLKS, 256, GTOT>>>(a1, a2, adj);
    aggregate_mma<<<(NN / 64) * H, 256, SM_TOT>>>(out);
}